// round 2
// baseline (speedup 1.0000x reference)
#include <cuda_runtime.h>

#define NN   4096
#define DIN  512
#define HID  256
#define DBOX 22

// ---- scratch (device globals; no allocation allowed) ----
__device__ float g_K[2][NN * HID];
__device__ float g_Q[2][NN * HID];
__device__ float g_V[2][NN * HID];
__device__ float g_M[2][DBOX * DBOX];
__device__ float g_BM[2][NN * DBOX];
__device__ float g_O[2][NN * HID];
__device__ float g_part[2][64];
__device__ float g_isum[2];

// ================= projection GEMM: C[4096,256] = A[4096,512] @ W[512,256] ==========
__global__ __launch_bounds__(256) void proj_kernel(const float* __restrict__ A,
                                                   const float* __restrict__ W,
                                                   int which, int branch) {
    float* C = (which == 0) ? g_K[branch] : (which == 1 ? g_Q[branch] : g_V[branch]);
    __shared__ __align__(16) float As[16][68];
    __shared__ __align__(16) float Ws[16][68];
    const int t = threadIdx.x;
    const int tx = t & 15, ty = t >> 4;
    const int r0 = blockIdx.y * 64;
    const int c0 = blockIdx.x * 64;
    float acc[4][4] = {};
    for (int k0 = 0; k0 < DIN; k0 += 16) {
#pragma unroll
        for (int l = 0; l < 4; ++l) {
            int e = t + l * 256;
            As[e & 15][e >> 4] = A[(r0 + (e >> 4)) * DIN + k0 + (e & 15)];
        }
#pragma unroll
        for (int l = 0; l < 4; ++l) {
            int e = t + l * 256;
            Ws[e >> 6][e & 63] = W[(k0 + (e >> 6)) * HID + c0 + (e & 63)];
        }
        __syncthreads();
#pragma unroll
        for (int kk = 0; kk < 16; ++kk) {
            float4 a4 = *(const float4*)&As[kk][ty * 4];
            float4 w4 = *(const float4*)&Ws[kk][tx * 4];
            float av[4] = {a4.x, a4.y, a4.z, a4.w};
            float wv[4] = {w4.x, w4.y, w4.z, w4.w};
#pragma unroll
            for (int mi = 0; mi < 4; ++mi)
#pragma unroll
                for (int ni = 0; ni < 4; ++ni) acc[mi][ni] += av[mi] * wv[ni];
        }
        __syncthreads();
    }
#pragma unroll
    for (int mi = 0; mi < 4; ++mi) {
        float4 v = make_float4(acc[mi][0], acc[mi][1], acc[mi][2], acc[mi][3]);
        *(float4*)&C[(r0 + ty * 4 + mi) * HID + c0 + tx * 4] = v;
    }
}

// ================= M = WG @ WG^T  (22x22, inner 256) ==============================
__global__ void gramm_kernel(const float* __restrict__ WG1, const float* __restrict__ WG2) {
    const float* WG = blockIdx.x ? WG2 : WG1;
    int t = threadIdx.x;
    if (t < DBOX * DBOX) {
        int i = t / DBOX, j = t % DBOX;
        float s = 0.f;
        for (int d = 0; d < HID; ++d) s += WG[i * HID + d] * WG[j * HID + d];
        g_M[blockIdx.x][t] = s;
    }
}

// ================= BM = box @ M   [4096, 22] ======================================
__global__ __launch_bounds__(256) void bm_kernel(const float* __restrict__ box) {
    __shared__ float Ms[DBOX * DBOX];
    int b = blockIdx.y, t = threadIdx.x;
    for (int i = t; i < DBOX * DBOX; i += 256) Ms[i] = g_M[b][i];
    __syncthreads();
    int e = blockIdx.x * 256 + t;  // grid.x = 352 -> exactly 4096*22
    int r = e / DBOX, c = e % DBOX;
    float s = 0.f;
#pragma unroll
    for (int k = 0; k < DBOX; ++k) s += box[r * DBOX + k] * Ms[k * DBOX + c];
    g_BM[b][e] = s;
}

// ================= fused attention: O = S @ V, partial sums =======================
// S_ij = relu((BM_i . box_j)/16) * exp((K_i . Q_j)/16), never materialized globally.
__global__ __launch_bounds__(256, 1) void attn_kernel(const float* __restrict__ box) {
    const int b = blockIdx.y;
    const int i0 = blockIdx.x * 64;
    const float* __restrict__ K = g_K[b];
    const float* __restrict__ Q = g_Q[b];
    const float* __restrict__ V = g_V[b];

    __shared__ __align__(16) float sBM[64][23];
    __shared__ __align__(16) float sBox[64][23];
    __shared__ __align__(16) float sKQ[2][32][68];   // stage A chunks; aliased as S[64][68]
    __shared__ __align__(16) float sV[16][256];
    __shared__ float sred[256];
    float (*sS)[68] = reinterpret_cast<float(*)[68]>(&sKQ[0][0][0]);

    const int t = threadIdx.x;
    const int tx = t & 15, ty = t >> 4;   // stage A: 16x16 threads, 4x4 micro
    const int cg = t & 31, rg = t >> 5;   // stage B: 8x32 threads, 8x8 micro

    for (int e = t; e < 64 * DBOX; e += 256)
        sBM[e / DBOX][e % DBOX] = g_BM[b][(i0 + e / DBOX) * DBOX + e % DBOX];

    float acc[8][8] = {};
    float sumLoc = 0.f;

#pragma unroll 1
    for (int j0 = 0; j0 < NN; j0 += 64) {
        float a[4][4] = {};
        float g[4][4] = {};
        for (int e = t; e < 64 * DBOX; e += 256)
            sBox[e / DBOX][e % DBOX] = box[(j0 + e / DBOX) * DBOX + e % DBOX];

        // ---- stage A: a = K_i . Q_j over d=0..255 in 32-wide chunks ----
#pragma unroll 1
        for (int d0 = 0; d0 < HID; d0 += 32) {
            __syncthreads();   // prior readers of sKQ/sS done before overwrite
#pragma unroll
            for (int l = 0; l < 8; ++l) {
                int e = t + l * 256;
                int dd = e & 31, r = e >> 5;
                sKQ[0][dd][r] = K[(i0 + r) * HID + d0 + dd];
                sKQ[1][dd][r] = Q[(j0 + r) * HID + d0 + dd];
            }
            __syncthreads();
#pragma unroll
            for (int kk = 0; kk < 32; ++kk) {
                float4 k4 = *(const float4*)&sKQ[0][kk][ty * 4];
                float4 q4 = *(const float4*)&sKQ[1][kk][tx * 4];
                float kv[4] = {k4.x, k4.y, k4.z, k4.w};
                float qv[4] = {q4.x, q4.y, q4.z, q4.w};
#pragma unroll
                for (int mi = 0; mi < 4; ++mi)
#pragma unroll
                    for (int ni = 0; ni < 4; ++ni) a[mi][ni] += kv[mi] * qv[ni];
            }
        }
        __syncthreads();

        // ---- gate gram via rank-22 trick: g = BM_i . box_j ----
#pragma unroll
        for (int dd = 0; dd < DBOX; ++dd) {
            float bmv[4], bxv[4];
#pragma unroll
            for (int mi = 0; mi < 4; ++mi) bmv[mi] = sBM[ty * 4 + mi][dd];
#pragma unroll
            for (int ni = 0; ni < 4; ++ni) bxv[ni] = sBox[tx * 4 + ni][dd];
#pragma unroll
            for (int mi = 0; mi < 4; ++mi)
#pragma unroll
                for (int ni = 0; ni < 4; ++ni) g[mi][ni] += bmv[mi] * bxv[ni];
        }

        // ---- combine: s = relu(g/16) * exp(a/16); store S tile, track sum ----
#pragma unroll
        for (int mi = 0; mi < 4; ++mi)
#pragma unroll
            for (int ni = 0; ni < 4; ++ni) {
                float gv = g[mi][ni];
                float s = (gv > 0.f) ? gv * 0.0625f * __expf(a[mi][ni] * 0.0625f) : 0.f;
                sumLoc += s;
                sS[ty * 4 + mi][tx * 4 + ni] = s;
            }
        __syncthreads();

        // ---- stage B: O[64x256] += S[64x64] @ V_j[64x256], V streamed 16 rows at a time ----
#pragma unroll 1
        for (int jc = 0; jc < 4; ++jc) {
#pragma unroll
            for (int l = 0; l < 4; ++l) {
                int idx = t + l * 256;          // float4 index over 16x64
                int rr = idx >> 6, c4 = idx & 63;
                *(float4*)&sV[rr][c4 * 4] =
                    *(const float4*)&V[(j0 + jc * 16 + rr) * HID + c4 * 4];
            }
            __syncthreads();
#pragma unroll
            for (int uu = 0; uu < 16; ++uu) {
                float sv[8];
#pragma unroll
                for (int i = 0; i < 8; ++i) sv[i] = sS[rg * 8 + i][jc * 16 + uu];  // broadcast
                float4 v0 = *(const float4*)&sV[uu][cg * 8];
                float4 v1 = *(const float4*)&sV[uu][cg * 8 + 4];
                float vv[8] = {v0.x, v0.y, v0.z, v0.w, v1.x, v1.y, v1.z, v1.w};
#pragma unroll
                for (int i = 0; i < 8; ++i)
#pragma unroll
                    for (int k = 0; k < 8; ++k) acc[i][k] += sv[i] * vv[k];
            }
            __syncthreads();
        }
    }

    // ---- write unnormalized O strip ----
#pragma unroll
    for (int i = 0; i < 8; ++i) {
        int row = i0 + rg * 8 + i;
        *(float4*)&g_O[b][row * HID + cg * 8] =
            make_float4(acc[i][0], acc[i][1], acc[i][2], acc[i][3]);
        *(float4*)&g_O[b][row * HID + cg * 8 + 4] =
            make_float4(acc[i][4], acc[i][5], acc[i][6], acc[i][7]);
    }

    // ---- deterministic partial-sum (no float atomics) ----
    sred[t] = sumLoc;
    __syncthreads();
    for (int s2 = 128; s2 > 0; s2 >>= 1) {
        if (t < s2) sred[t] += sred[t + s2];
        __syncthreads();
    }
    if (t == 0) g_part[b][blockIdx.x] = sred[0];
}

// ================= deterministic final sum -> 0.1 / sum ===========================
__global__ void sum_kernel() {
    if (threadIdx.x == 0) {
        float s = 0.f;
        for (int i = 0; i < 64; ++i) s += g_part[blockIdx.x][i];
        g_isum[blockIdx.x] = 0.1f / s;
    }
}

// ================= out = x + 0.1 * O/sum (concat over branches) ===================
__global__ __launch_bounds__(256) void final_kernel(const float* __restrict__ x,
                                                    float* __restrict__ out) {
    int idx = blockIdx.x * 256 + threadIdx.x;
    int r = idx >> 9, c = idx & 511;
    int b = c >> 8, cc = c & 255;
    out[idx] = fmaf(g_O[b][r * HID + cc], g_isum[b], x[idx]);
}

// =================================================================================
extern "C" void kernel_launch(void* const* d_in, const int* in_sizes, int n_in,
                              void* d_out, int out_size) {
    const float* x   = (const float*)d_in[0];
    const float* box = (const float*)d_in[1];
    const float* WG1 = (const float*)d_in[2];
    const float* WK1 = (const float*)d_in[3];
    const float* WQ1 = (const float*)d_in[4];
    const float* WV1 = (const float*)d_in[5];
    const float* WG2 = (const float*)d_in[6];
    const float* WK2 = (const float*)d_in[7];
    const float* WQ2 = (const float*)d_in[8];
    const float* WV2 = (const float*)d_in[9];
    float* out = (float*)d_out;

    dim3 pg(4, 64);
    proj_kernel<<<pg, 256>>>(x, WK1, 0, 0);
    proj_kernel<<<pg, 256>>>(x, WQ1, 1, 0);
    proj_kernel<<<pg, 256>>>(x, WV1, 2, 0);
    proj_kernel<<<pg, 256>>>(x, WK2, 0, 1);
    proj_kernel<<<pg, 256>>>(x, WQ2, 1, 1);
    proj_kernel<<<pg, 256>>>(x, WV2, 2, 1);
    gramm_kernel<<<2, 512>>>(WG1, WG2);
    bm_kernel<<<dim3(352, 2), 256>>>(box);
    attn_kernel<<<dim3(64, 2), 256>>>(box);
    sum_kernel<<<2, 32>>>();
    final_kernel<<<8192, 256>>>(x, out);
}

// round 4
// speedup vs baseline: 5.9538x; 5.9538x over previous
#include <cuda_runtime.h>
#include <cuda_bf16.h>
#include <cstdint>

#define NN   4096
#define DIN  512
#define HID  256
#define DBOX 22

// ---- scratch (device globals) ----
__device__ __nv_bfloat16 g_xb[NN * DIN];
__device__ __nv_bfloat16 g_Wb[6][DIN * HID];    // W in bf16, [k][n] as given
__device__ __nv_bfloat16 g_Kb[2][NN * HID];
__device__ __nv_bfloat16 g_Qb[2][NN * HID];
__device__ __nv_bfloat16 g_Vb[2][NN * HID];
__device__ __nv_bfloat16 g_BMb[2][NN * 32];     // box@M, zero-padded to 32 cols
__device__ __nv_bfloat16 g_boxb[NN * 32];       // box, zero-padded to 32 cols
__device__ float g_M[2][DBOX * DBOX];
__device__ float g_O[2][NN * HID];
__device__ float g_part[2][64];
__device__ float g_isum[2];

// ================= PTX helpers =====================================================
__device__ __forceinline__ uint32_t s2u(const void* p) {
    uint32_t a;
    asm("{ .reg .u64 t; cvta.to.shared.u64 t, %1; cvt.u32.u64 %0, t; }" : "=r"(a) : "l"(p));
    return a;
}
__device__ __forceinline__ void cp16(uint32_t s, const void* g) {
    asm volatile("cp.async.cg.shared.global [%0], [%1], 16;" :: "r"(s), "l"(g));
}
#define CP_COMMIT asm volatile("cp.async.commit_group;" ::: "memory")
#define CP_WAIT0  asm volatile("cp.async.wait_group 0;"  ::: "memory")
#define CP_WAIT1  asm volatile("cp.async.wait_group 1;"  ::: "memory")

__device__ __forceinline__ void ldsm4(uint32_t* r, uint32_t a) {
    asm volatile("ldmatrix.sync.aligned.m8n8.x4.shared.b16 {%0,%1,%2,%3}, [%4];"
                 : "=r"(r[0]), "=r"(r[1]), "=r"(r[2]), "=r"(r[3]) : "r"(a));
}
__device__ __forceinline__ void ldsm4t(uint32_t* r, uint32_t a) {
    asm volatile("ldmatrix.sync.aligned.m8n8.x4.trans.shared.b16 {%0,%1,%2,%3}, [%4];"
                 : "=r"(r[0]), "=r"(r[1]), "=r"(r[2]), "=r"(r[3]) : "r"(a));
}
__device__ __forceinline__ void mma16816(float* d, const uint32_t* a, const uint32_t* b) {
    asm volatile(
        "mma.sync.aligned.m16n8k16.row.col.f32.bf16.bf16.f32 "
        "{%0,%1,%2,%3}, {%4,%5,%6,%7}, {%8,%9}, {%0,%1,%2,%3};"
        : "+f"(d[0]), "+f"(d[1]), "+f"(d[2]), "+f"(d[3])
        : "r"(a[0]), "r"(a[1]), "r"(a[2]), "r"(a[3]), "r"(b[0]), "r"(b[1]));
}
__device__ __forceinline__ uint32_t packbf2(float x, float y) {
    __nv_bfloat162 p = __floats2bfloat162_rn(x, y);
    return *(uint32_t*)&p;
}

// ================= conversions ====================================================
__global__ __launch_bounds__(256) void conv_x(const float* __restrict__ x) {
    int idx = blockIdx.x * 256 + threadIdx.x;          // float4 index
    float4 v = ((const float4*)x)[idx];
    *(uint32_t*)&g_xb[idx * 4]     = packbf2(v.x, v.y);
    *(uint32_t*)&g_xb[idx * 4 + 2] = packbf2(v.z, v.w);
}

__global__ __launch_bounds__(256) void conv_w(
    const float* __restrict__ W0, const float* __restrict__ W1, const float* __restrict__ W2,
    const float* __restrict__ W3, const float* __restrict__ W4, const float* __restrict__ W5) {
    const int z = blockIdx.z;
    const float* W = (z == 0) ? W0 : (z == 1) ? W1 : (z == 2) ? W2 : (z == 3) ? W3 : (z == 4) ? W4 : W5;
    int idx = blockIdx.x * 256 + threadIdx.x;          // float4 index over 512*256/4
    float4 v = ((const float4*)W)[idx];
    *(uint32_t*)&g_Wb[z][idx * 4]     = packbf2(v.x, v.y);
    *(uint32_t*)&g_Wb[z][idx * 4 + 2] = packbf2(v.z, v.w);
}

// ================= M = WG @ WG^T (22x22, fp32) ====================================
__global__ void gramm_kernel(const float* __restrict__ WG1, const float* __restrict__ WG2) {
    const float* WG = blockIdx.x ? WG2 : WG1;
    int t = threadIdx.x;
    if (t < DBOX * DBOX) {
        int i = t / DBOX, j = t % DBOX;
        float s = 0.f;
        for (int d = 0; d < HID; ++d) s += WG[i * HID + d] * WG[j * HID + d];
        g_M[blockIdx.x][t] = s;
    }
}

// ================= pad box / BM -> [4096,32] bf16 =================================
__global__ __launch_bounds__(256) void pad_kernel(const float* __restrict__ box) {
    __shared__ float Ms[DBOX * DBOX];
    int y = blockIdx.y, t = threadIdx.x;   // y: 0=box, 1=BM br0, 2=BM br1
    if (y > 0) {
        for (int i = t; i < DBOX * DBOX; i += 256) Ms[i] = g_M[y - 1][i];
        __syncthreads();
    }
    int e = blockIdx.x * 256 + t;          // 4096*32 total, grid.x = 512
    int r = e >> 5, c = e & 31;
    float v = 0.f;
    if (c < DBOX) {
        if (y == 0) v = box[r * DBOX + c];
        else {
            float s = 0.f;
#pragma unroll
            for (int k = 0; k < DBOX; ++k) s += box[r * DBOX + k] * Ms[k * DBOX + c];
            v = s;
        }
    }
    __nv_bfloat16 h = __float2bfloat16(v);
    if (y == 0) g_boxb[e] = h;
    else g_BMb[y - 1][e] = h;
}

// ================= projection: C[4096,256] = xb @ W  (mma.sync bf16) ==============
// tile 128(m) x 64(n), k=512 in 8 chunks of 64, double-buffered cp.async.
// smem: sA 2 x [128][72] bf16 (36864 B), sB 2 x [64][72] (18432 B) -> 55296 B
__global__ void __launch_bounds__(256, 1) proj_kernel(int) {
    extern __shared__ char smem[];
    const int z = blockIdx.z;
    const int m0 = blockIdx.x * 128, n0 = blockIdx.y * 64;
    const int br = z / 3, wh = z % 3;
    __nv_bfloat16* C = (wh == 0) ? g_Kb[br] : (wh == 1) ? g_Qb[br] : g_Vb[br];
    const __nv_bfloat16* __restrict__ Wb = g_Wb[z];
    const int t = threadIdx.x, w = t >> 5, lane = t & 31;
    uint32_t sb = s2u(smem);
    const int mi = w >> 1, njw = w & 1;
    float acc[2][4][4] = {};

#define PROJ_ISSUE(ck)                                                               \
    {                                                                                \
        int k0 = (ck) * 64, buf = (ck) & 1;                                          \
        _Pragma("unroll") for (int l = 0; l < 4; ++l) {                              \
            int idx = t + l * 256;                                                   \
            int r = idx >> 3, c8 = (idx & 7) << 3;                                   \
            cp16(sb + buf * 18432 + (r * 72 + c8) * 2, g_xb + (m0 + r) * DIN + k0 + c8); \
        }                                                                            \
        _Pragma("unroll") for (int l = 0; l < 2; ++l) {                              \
            int idx = t + l * 256;                                                   \
            int r = idx >> 3, c8 = (idx & 7) << 3;                                   \
            cp16(sb + 36864 + buf * 9216 + (r * 72 + c8) * 2, Wb + (k0 + r) * HID + n0 + c8); \
        }                                                                            \
        CP_COMMIT;                                                                   \
    }

    PROJ_ISSUE(0);
    for (int ck = 0; ck < 8; ++ck) {
        if (ck < 7) { PROJ_ISSUE(ck + 1); CP_WAIT1; } else { CP_WAIT0; }
        __syncthreads();
        const uint32_t aB = sb + (ck & 1) * 18432;
        const uint32_t bB = sb + 36864 + (ck & 1) * 9216;
#pragma unroll
        for (int kt = 0; kt < 4; ++kt) {
            uint32_t a[2][4];
#pragma unroll
            for (int mt = 0; mt < 2; ++mt) {
                int row = mi * 32 + mt * 16 + (lane & 15);
                int col = kt * 16 + ((lane >> 4) << 3);
                ldsm4(a[mt], aB + (row * 72 + col) * 2);
            }
#pragma unroll
            for (int nb = 0; nb < 2; ++nb) {
                uint32_t bw[4];
                int wrow = kt * 16 + ((lane >> 3) & 1) * 8 + (lane & 7);
                int wcol = njw * 32 + nb * 16 + ((lane >> 4) << 3);
                ldsm4t(bw, bB + (wrow * 72 + wcol) * 2);
#pragma unroll
                for (int mt = 0; mt < 2; ++mt) {
                    mma16816(acc[mt][nb * 2],     a[mt], bw);
                    mma16816(acc[mt][nb * 2 + 1], a[mt], bw + 2);
                }
            }
        }
        __syncthreads();
    }
#pragma unroll
    for (int mt = 0; mt < 2; ++mt)
#pragma unroll
        for (int nt = 0; nt < 4; ++nt) {
            int row = m0 + mi * 32 + mt * 16 + (lane >> 2);
            int col = n0 + njw * 32 + nt * 8 + (lane & 3) * 2;
            *(uint32_t*)&C[row * HID + col]       = packbf2(acc[mt][nt][0], acc[mt][nt][1]);
            *(uint32_t*)&C[(row + 8) * HID + col] = packbf2(acc[mt][nt][2], acc[mt][nt][3]);
        }
}

// ================= fused attention (mma.sync bf16, register-fragment flash) =======
// smem byte map:
//   sK   [64][264]  @0       33792
//   sBM  [64][40]   @33792    5120
//   sQ  2x[64][264] @38912   67584
//   sBox 2x[64][40] @106496  10240
//   sV   [64][264]  @116736  33792
//   sS   [64][72]   @150528   9216
//   sred 256 floats @159744   1024   -> total 160768
__global__ void __launch_bounds__(256, 1) attn_kernel(int) {
    extern __shared__ char smem[];
    const int b = blockIdx.y;
    const int i0 = blockIdx.x * 64;
    const int t = threadIdx.x, w = t >> 5, lane = t & 31;
    uint32_t sb = s2u(smem);
    const __nv_bfloat16* __restrict__ Kg = g_Kb[b];
    const __nv_bfloat16* __restrict__ Qg = g_Qb[b];
    const __nv_bfloat16* __restrict__ Vg = g_Vb[b];
    const __nv_bfloat16* __restrict__ BMg = g_BMb[b];

    const int mi = w >> 2, nj = w & 3;      // stage1: 2(m) x 4(j16)
    const int nd = w & 3;                    // stage2: 2(m) x 4(d64), mi reused
    float acc[2][8][4] = {};
    float sumLoc = 0.f;

    // prologue: K + BM (group), Q0+box0 (group), V0 (group)
    {
#pragma unroll
        for (int l = 0; l < 8; ++l) {
            int idx = t + l * 256;
            int r = idx >> 5, c8 = (idx & 31) << 3;
            cp16(sb + (r * 264 + c8) * 2, Kg + (i0 + r) * HID + c8);
        }
        { int r = t >> 2, c8 = (t & 3) << 3;
          cp16(sb + 33792 + (r * 40 + c8) * 2, BMg + (i0 + r) * 32 + c8); }
        CP_COMMIT;
    }
#define ATTN_ISSUE_Q(j0, buf)                                                        \
    {                                                                                \
        _Pragma("unroll") for (int l = 0; l < 8; ++l) {                              \
            int idx = t + l * 256;                                                   \
            int r = idx >> 5, c8 = (idx & 31) << 3;                                  \
            cp16(sb + 38912 + (buf) * 33792 + (r * 264 + c8) * 2, Qg + ((j0) + r) * HID + c8); \
        }                                                                            \
        { int r = t >> 2, c8 = (t & 3) << 3;                                         \
          cp16(sb + 106496 + (buf) * 5120 + (r * 40 + c8) * 2, g_boxb + ((j0) + r) * 32 + c8); } \
        CP_COMMIT;                                                                   \
    }
#define ATTN_ISSUE_V(j0)                                                             \
    {                                                                                \
        _Pragma("unroll") for (int l = 0; l < 8; ++l) {                              \
            int idx = t + l * 256;                                                   \
            int r = idx >> 5, c8 = (idx & 31) << 3;                                  \
            cp16(sb + 116736 + (r * 264 + c8) * 2, Vg + ((j0) + r) * HID + c8);      \
        }                                                                            \
        CP_COMMIT;                                                                   \
    }
    ATTN_ISSUE_Q(0, 0);
    ATTN_ISSUE_V(0);

    for (int jt = 0; jt < 64; ++jt) {
        const int cur = jt & 1;
        CP_WAIT1;                 // Q(jt)/box(jt) (and K/BM on first iter) complete
        __syncthreads();
        ATTN_ISSUE_Q(((jt + 1) & 63) * 64, cur ^ 1);

        // ---- stage 1: WA = K.Q^T (k=256) and G = BM.box^T (k=32) ----
        float wa[2][2][4] = {};
        float gg[2][2][4] = {};
        const uint32_t qB = sb + 38912 + cur * 33792;
        const uint32_t xB = sb + 106496 + cur * 5120;
#pragma unroll
        for (int kt = 0; kt < 16; ++kt) {
            uint32_t a[2][4], bq[4];
#pragma unroll
            for (int mt = 0; mt < 2; ++mt) {
                int row = mi * 32 + mt * 16 + (lane & 15);
                int col = kt * 16 + ((lane >> 4) << 3);
                ldsm4(a[mt], sb + (row * 264 + col) * 2);
            }
            {
                int brow = nj * 16 + ((lane >> 4) << 3) + (lane & 7);
                int bcol = kt * 16 + ((lane >> 3) & 1) * 8;
                ldsm4(bq, qB + (brow * 264 + bcol) * 2);
            }
#pragma unroll
            for (int mt = 0; mt < 2; ++mt) {
                mma16816(wa[mt][0], a[mt], bq);
                mma16816(wa[mt][1], a[mt], bq + 2);
            }
        }
#pragma unroll
        for (int kt = 0; kt < 2; ++kt) {
            uint32_t a[2][4], bx[4];
#pragma unroll
            for (int mt = 0; mt < 2; ++mt) {
                int row = mi * 32 + mt * 16 + (lane & 15);
                int col = kt * 16 + ((lane >> 4) << 3);
                ldsm4(a[mt], sb + 33792 + (row * 40 + col) * 2);
            }
            {
                int brow = nj * 16 + ((lane >> 4) << 3) + (lane & 7);
                int bcol = kt * 16 + ((lane >> 3) & 1) * 8;
                ldsm4(bx, xB + (brow * 40 + bcol) * 2);
            }
#pragma unroll
            for (int mt = 0; mt < 2; ++mt) {
                mma16816(gg[mt][0], a[mt], bx);
                mma16816(gg[mt][1], a[mt], bx + 2);
            }
        }

        CP_WAIT1;                 // V(jt) complete (Q(jt+1) still pending)

        // ---- elementwise: S = relu(G/16) * exp(WA/16) -> bf16 sS ----
#pragma unroll
        for (int mt = 0; mt < 2; ++mt)
#pragma unroll
            for (int nt = 0; nt < 2; ++nt) {
                float s[4];
#pragma unroll
                for (int q = 0; q < 4; ++q) {
                    float gv = gg[mt][nt][q];
                    s[q] = gv > 0.f ? gv * 0.0625f * __expf(wa[mt][nt][q] * 0.0625f) : 0.f;
                    sumLoc += s[q];
                }
                int row = mi * 32 + mt * 16 + (lane >> 2);
                int col = nj * 16 + nt * 8 + (lane & 3) * 2;
                *(uint32_t*)(smem + 150528 + (row * 72 + col) * 2)       = packbf2(s[0], s[1]);
                *(uint32_t*)(smem + 150528 + ((row + 8) * 72 + col) * 2) = packbf2(s[2], s[3]);
            }
        __syncthreads();          // S visible to all warps; V arrival fenced

        // ---- stage 2: O += S @ V ----
#pragma unroll
        for (int kt = 0; kt < 4; ++kt) {
            uint32_t a2[2][4];
#pragma unroll
            for (int mt = 0; mt < 2; ++mt) {
                int row = mi * 32 + mt * 16 + (lane & 15);
                int col = kt * 16 + ((lane >> 4) << 3);
                ldsm4(a2[mt], sb + 150528 + (row * 72 + col) * 2);
            }
#pragma unroll
            for (int nb = 0; nb < 4; ++nb) {
                uint32_t bv[4];
                int vrow = kt * 16 + ((lane >> 3) & 1) * 8 + (lane & 7);
                int vcol = nd * 64 + nb * 16 + ((lane >> 4) << 3);
                ldsm4t(bv, sb + 116736 + (vrow * 264 + vcol) * 2);
#pragma unroll
                for (int mt = 0; mt < 2; ++mt) {
                    mma16816(acc[mt][nb * 2],     a2[mt], bv);
                    mma16816(acc[mt][nb * 2 + 1], a2[mt], bv + 2);
                }
            }
        }
        __syncthreads();          // done reading sV/sS
        ATTN_ISSUE_V(((jt + 1) & 63) * 64);
    }

    // ---- epilogue: unnormalized O ----
#pragma unroll
    for (int mt = 0; mt < 2; ++mt)
#pragma unroll
        for (int j8 = 0; j8 < 8; ++j8) {
            int row = i0 + mi * 32 + mt * 16 + (lane >> 2);
            int col = nd * 64 + j8 * 8 + (lane & 3) * 2;
            *(float2*)&g_O[b][row * HID + col]       = make_float2(acc[mt][j8][0], acc[mt][j8][1]);
            *(float2*)&g_O[b][(row + 8) * HID + col] = make_float2(acc[mt][j8][2], acc[mt][j8][3]);
        }

    // ---- deterministic partial sum ----
    float* sred = (float*)(smem + 159744);
    sred[t] = sumLoc;
    __syncthreads();
    for (int s2 = 128; s2 > 0; s2 >>= 1) {
        if (t < s2) sred[t] += sred[t + s2];
        __syncthreads();
    }
    if (t == 0) g_part[b][blockIdx.x] = sred[0];
}

// ================= final sum -> 0.1/sum ===========================================
__global__ void sum_kernel() {
    if (threadIdx.x == 0) {
        float s = 0.f;
        for (int i = 0; i < 64; ++i) s += g_part[blockIdx.x][i];
        g_isum[blockIdx.x] = 0.1f / s;
    }
}

// ================= out = x + 0.1 * O/sum ==========================================
__global__ __launch_bounds__(256) void final_kernel(const float* __restrict__ x,
                                                    float* __restrict__ out) {
    int idx = blockIdx.x * 256 + threadIdx.x;
    int r = idx >> 9, c = idx & 511;
    int b = c >> 8, cc = c & 255;
    out[idx] = fmaf(g_O[b][r * HID + cc], g_isum[b], x[idx]);
}

// =================================================================================
extern "C" void kernel_launch(void* const* d_in, const int* in_sizes, int n_in,
                              void* d_out, int out_size) {
    const float* x   = (const float*)d_in[0];
    const float* box = (const float*)d_in[1];
    const float* WG1 = (const float*)d_in[2];
    const float* WK1 = (const float*)d_in[3];
    const float* WQ1 = (const float*)d_in[4];
    const float* WV1 = (const float*)d_in[5];
    const float* WG2 = (const float*)d_in[6];
    const float* WK2 = (const float*)d_in[7];
    const float* WQ2 = (const float*)d_in[8];
    const float* WV2 = (const float*)d_in[9];
    float* out = (float*)d_out;

    static int inited = 0;
    if (!inited) {
        cudaFuncSetAttribute(proj_kernel, cudaFuncAttributeMaxDynamicSharedMemorySize, 55296);
        cudaFuncSetAttribute(attn_kernel, cudaFuncAttributeMaxDynamicSharedMemorySize, 160768);
        inited = 1;
    }

    conv_x<<<2048, 256>>>(x);
    conv_w<<<dim3(128, 1, 6), 256>>>(WK1, WQ1, WV1, WK2, WQ2, WV2);
    gramm_kernel<<<2, 512>>>(WG1, WG2);
    pad_kernel<<<dim3(512, 3), 256>>>(box);
    proj_kernel<<<dim3(32, 4, 6), 256, 55296>>>(0);
    attn_kernel<<<dim3(64, 2), 256, 160768>>>(0);
    sum_kernel<<<2, 32>>>();
    final_kernel<<<8192, 256>>>(x, out);
}